// round 1
// baseline (speedup 1.0000x reference)
#include <cuda_runtime.h>

constexpr int S_LEN = 2048;   // state_len (output rows)
constexpr int SEQ   = 4096;   // seq_len   (output cols)
constexpr int HID   = 2048;   // hidden

// Scratch (allocation-free rule: __device__ globals)
__device__ float g_T[(size_t)S_LEN * HID];       // out_state @ W        [2048, 2048]
__device__ float g_scores[(size_t)S_LEN * SEQ];  // pre-softmax scores   [2048, 4096]
__device__ float g_c[S_LEN];                     // out_state . b        [2048]

// ---------------------------------------------------------------------------
// c[i] = out_state[i] . b
// ---------------------------------------------------------------------------
__global__ __launch_bounds__(256) void dot_bias_kernel(const float* __restrict__ A,
                                                       const float* __restrict__ b) {
    const int i = blockIdx.x;
    const float* row = A + (size_t)i * HID;
    float s = 0.f;
    for (int h = threadIdx.x * 4; h < HID; h += 256 * 4) {
        float4 x = *reinterpret_cast<const float4*>(row + h);
        float4 y = *reinterpret_cast<const float4*>(b + h);
        s += x.x * y.x + x.y * y.y + x.z * y.z + x.w * y.w;
    }
    __shared__ float red[8];
    #pragma unroll
    for (int o = 16; o; o >>= 1) s += __shfl_xor_sync(0xffffffffu, s, o);
    if ((threadIdx.x & 31) == 0) red[threadIdx.x >> 5] = s;
    __syncthreads();
    if (threadIdx.x == 0) {
        float t = 0.f;
        #pragma unroll
        for (int k = 0; k < 8; k++) t += red[k];
        g_c[i] = t;
    }
}

// ---------------------------------------------------------------------------
// Tiled fp32 GEMM: C[M,N] = A[M,K] @ B (+ bias[row])
//   BT=false : B is [K,N] row-major (NN)
//   BT=true  : B is [N,K] row-major (NT, i.e. C = A @ B^T)
// Block tile 128x128, K-tile 16, 256 threads, 8x8 per thread.
// Requires M,N % 128 == 0, K % 16 == 0 (true for all shapes here).
// ---------------------------------------------------------------------------
template <bool BT>
__global__ __launch_bounds__(256) void gemm128(const float* __restrict__ A,
                                               const float* __restrict__ B,
                                               float* __restrict__ C,
                                               const float* __restrict__ bias,
                                               int M, int N, int K) {
    __shared__ float As[16][128];
    __shared__ float Bs[16][128];

    const int tid = threadIdx.x;
    const int tx = tid & 15;       // 0..15 -> output col group
    const int ty = tid >> 4;       // 0..15 -> output row group
    const int rowBase = blockIdx.y * 128;
    const int colBase = blockIdx.x * 128;

    const int ar = tid >> 2;       // 0..63 : row within tile for strided loads
    const int ac = tid & 3;        // 0..3  : float4 index along K
    const int br = tid >> 5;       // 0..7  : k-row for NN B loads
    const int bc = tid & 31;       // 0..31 : float4 index along N

    float acc[8][8];
    #pragma unroll
    for (int i = 0; i < 8; i++)
        #pragma unroll
        for (int j = 0; j < 8; j++) acc[i][j] = 0.f;

    for (int k0 = 0; k0 < K; k0 += 16) {
        // A tile [128 x 16] -> As[k][m]
        #pragma unroll
        for (int rr = 0; rr < 2; rr++) {
            const int r = ar + rr * 64;
            float4 v = *reinterpret_cast<const float4*>(
                A + (size_t)(rowBase + r) * K + k0 + ac * 4);
            As[ac * 4 + 0][r] = v.x;
            As[ac * 4 + 1][r] = v.y;
            As[ac * 4 + 2][r] = v.z;
            As[ac * 4 + 3][r] = v.w;
        }
        if (!BT) {
            // B tile [16 x 128] -> Bs[k][n], contiguous
            #pragma unroll
            for (int rr = 0; rr < 2; rr++) {
                const int r = br + rr * 8;
                float4 v = *reinterpret_cast<const float4*>(
                    B + (size_t)(k0 + r) * N + colBase + bc * 4);
                *reinterpret_cast<float4*>(&Bs[r][bc * 4]) = v;
            }
        } else {
            // B is [N,K]: Bs[k][n] = B[colBase+n][k0+k]
            #pragma unroll
            for (int rr = 0; rr < 2; rr++) {
                const int n = ar + rr * 64;
                float4 v = *reinterpret_cast<const float4*>(
                    B + (size_t)(colBase + n) * K + k0 + ac * 4);
                Bs[ac * 4 + 0][n] = v.x;
                Bs[ac * 4 + 1][n] = v.y;
                Bs[ac * 4 + 2][n] = v.z;
                Bs[ac * 4 + 3][n] = v.w;
            }
        }
        __syncthreads();

        #pragma unroll
        for (int kk = 0; kk < 16; kk++) {
            float a[8], bb[8];
            #pragma unroll
            for (int i = 0; i < 8; i++) a[i] = As[kk][ty * 8 + i];
            #pragma unroll
            for (int j = 0; j < 8; j++) bb[j] = Bs[kk][tx * 8 + j];
            #pragma unroll
            for (int i = 0; i < 8; i++)
                #pragma unroll
                for (int j = 0; j < 8; j++)
                    acc[i][j] = fmaf(a[i], bb[j], acc[i][j]);
        }
        __syncthreads();
    }

    #pragma unroll
    for (int i = 0; i < 8; i++) {
        const int row = rowBase + ty * 8 + i;
        const float rb = bias ? bias[row] : 0.f;
        #pragma unroll
        for (int j = 0; j < 8; j += 4) {
            float4 v = make_float4(acc[i][j + 0] + rb, acc[i][j + 1] + rb,
                                   acc[i][j + 2] + rb, acc[i][j + 3] + rb);
            *reinterpret_cast<float4*>(C + (size_t)row * N + colBase + tx * 8 + j) = v;
        }
    }
}

// ---------------------------------------------------------------------------
// Row softmax over 4096 columns. One block (256 threads) per row; each thread
// keeps its 16 values in registers across the two passes.
// ---------------------------------------------------------------------------
__global__ __launch_bounds__(256) void softmax_kernel(const float* __restrict__ scores,
                                                      float* __restrict__ out) {
    const int i = blockIdx.x;
    const float4* row = reinterpret_cast<const float4*>(scores + (size_t)i * SEQ);
    float4* orow = reinterpret_cast<float4*>(out + (size_t)i * SEQ);

    float4 v[4];
    float m = -1e30f;
    #pragma unroll
    for (int t = 0; t < 4; t++) {
        v[t] = row[threadIdx.x + t * 256];
        m = fmaxf(m, fmaxf(fmaxf(v[t].x, v[t].y), fmaxf(v[t].z, v[t].w)));
    }

    __shared__ float red[8];
    #pragma unroll
    for (int o = 16; o; o >>= 1) m = fmaxf(m, __shfl_xor_sync(0xffffffffu, m, o));
    if ((threadIdx.x & 31) == 0) red[threadIdx.x >> 5] = m;
    __syncthreads();
    float m_all = red[0];
    #pragma unroll
    for (int k = 1; k < 8; k++) m_all = fmaxf(m_all, red[k]);
    __syncthreads();  // everyone has read red[] before reuse

    float s = 0.f;
    #pragma unroll
    for (int t = 0; t < 4; t++) {
        v[t].x = __expf(v[t].x - m_all);
        v[t].y = __expf(v[t].y - m_all);
        v[t].z = __expf(v[t].z - m_all);
        v[t].w = __expf(v[t].w - m_all);
        s += v[t].x + v[t].y + v[t].z + v[t].w;
    }
    #pragma unroll
    for (int o = 16; o; o >>= 1) s += __shfl_xor_sync(0xffffffffu, s, o);
    if ((threadIdx.x & 31) == 0) red[threadIdx.x >> 5] = s;
    __syncthreads();
    float s_all = 0.f;
    #pragma unroll
    for (int k = 0; k < 8; k++) s_all += red[k];
    const float inv = 1.0f / s_all;

    #pragma unroll
    for (int t = 0; t < 4; t++) {
        float4 o4 = make_float4(v[t].x * inv, v[t].y * inv, v[t].z * inv, v[t].w * inv);
        orow[threadIdx.x + t * 256] = o4;
    }
}

// ---------------------------------------------------------------------------
extern "C" void kernel_launch(void* const* d_in, const int* in_sizes, int n_in,
                              void* d_out, int out_size) {
    const float* out_state = (const float*)d_in[0];  // [2048, 2048]
    const float* history   = (const float*)d_in[1];  // [4096, 2048]
    const float* W         = (const float*)d_in[2];  // [2048, 2048]
    const float* b         = (const float*)d_in[3];  // [2048]
    float* out = (float*)d_out;                      // [2048, 4096]

    float *T_ptr, *scores_ptr, *c_ptr;
    cudaGetSymbolAddress((void**)&T_ptr, g_T);
    cudaGetSymbolAddress((void**)&scores_ptr, g_scores);
    cudaGetSymbolAddress((void**)&c_ptr, g_c);

    // c[i] = out_state[i] . b
    dot_bias_kernel<<<S_LEN, 256>>>(out_state, b);

    // T = out_state @ W          (NN: W is [K=H, N=H] row-major)
    gemm128<false><<<dim3(HID / 128, S_LEN / 128), 256>>>(
        out_state, W, T_ptr, nullptr, S_LEN, HID, HID);

    // scores = T @ history^T + c (NT: history is [N=SEQ, K=H] row-major)
    gemm128<true><<<dim3(SEQ / 128, S_LEN / 128), 256>>>(
        T_ptr, history, scores_ptr, c_ptr, S_LEN, SEQ, HID);

    // out = softmax(scores, axis=-1)
    softmax_kernel<<<S_LEN, 256>>>(scores_ptr, out);
}

// round 3
// speedup vs baseline: 1.3292x; 1.3292x over previous
#include <cuda_runtime.h>
#include <cuda_bf16.h>
#include <cstdint>

constexpr int S_LEN = 2048;
constexpr int SEQ   = 4096;
constexpr int HID   = 2048;
constexpr int KDIM  = 2048;

// ---------------------------------------------------------------------------
// Scratch (__device__ globals; allocation-free rule)
// ---------------------------------------------------------------------------
__device__ __nv_bfloat16 g_osH[(size_t)S_LEN * HID];
__device__ __nv_bfloat16 g_osM[(size_t)S_LEN * HID];
__device__ __nv_bfloat16 g_osL[(size_t)S_LEN * HID];
__device__ __nv_bfloat16 g_wtH[(size_t)HID * HID];   // wt[k][h] = W[h][k]
__device__ __nv_bfloat16 g_wtM[(size_t)HID * HID];
__device__ __nv_bfloat16 g_wtL[(size_t)HID * HID];
__device__ __nv_bfloat16 g_hiH[(size_t)SEQ * HID];
__device__ __nv_bfloat16 g_hiM[(size_t)SEQ * HID];
__device__ __nv_bfloat16 g_hiL[(size_t)SEQ * HID];
__device__ __nv_bfloat16 g_tH[(size_t)S_LEN * HID];
__device__ __nv_bfloat16 g_tM[(size_t)S_LEN * HID];
__device__ __nv_bfloat16 g_tL[(size_t)S_LEN * HID];
__device__ float g_scores[(size_t)S_LEN * SEQ];
__device__ float g_c[S_LEN];

// ---------------------------------------------------------------------------
// PTX helpers (sm_80-baseline features only: legal on .target sm_103)
// ---------------------------------------------------------------------------
__device__ __forceinline__ uint32_t smem_to_u32(const void* p) {
    uint32_t a;
    asm("{ .reg .u64 t; cvta.to.shared.u64 t, %1; cvt.u32.u64 %0, t; }" : "=r"(a) : "l"(p));
    return a;
}
__device__ __forceinline__ void cp16(uint32_t dst, const void* src) {
    asm volatile("cp.async.cg.shared.global [%0], [%1], 16;" :: "r"(dst), "l"(src));
}
__device__ __forceinline__ void cp_commit() {
    asm volatile("cp.async.commit_group;" ::: "memory");
}
template <int N>
__device__ __forceinline__ void cp_wait() {
    asm volatile("cp.async.wait_group %0;" :: "n"(N) : "memory");
}
__device__ __forceinline__ void ldm4(uint32_t* r, uint32_t addr) {
    asm volatile("ldmatrix.sync.aligned.m8n8.x4.shared.b16 {%0,%1,%2,%3}, [%4];"
                 : "=r"(r[0]), "=r"(r[1]), "=r"(r[2]), "=r"(r[3]) : "r"(addr));
}
__device__ __forceinline__ void mma16816(float* d, const uint32_t* a, const uint32_t* b) {
    asm volatile(
        "mma.sync.aligned.m16n8k16.row.col.f32.bf16.bf16.f32 "
        "{%0,%1,%2,%3}, {%4,%5,%6,%7}, {%8,%9}, {%0,%1,%2,%3};"
        : "+f"(d[0]), "+f"(d[1]), "+f"(d[2]), "+f"(d[3])
        : "r"(a[0]), "r"(a[1]), "r"(a[2]), "r"(a[3]), "r"(b[0]), "r"(b[1]));
}

// ---------------------------------------------------------------------------
// 3-way bf16 split helpers
// ---------------------------------------------------------------------------
__device__ __forceinline__ void split3(float a, __nv_bfloat16& h, __nv_bfloat16& m,
                                       __nv_bfloat16& l) {
    h = __float2bfloat16(a);
    float r = a - __bfloat162float(h);
    m = __float2bfloat16(r);
    float r2 = r - __bfloat162float(m);
    l = __float2bfloat16(r2);
}

__global__ __launch_bounds__(256) void split3_kernel(const float* __restrict__ in,
                                                     __nv_bfloat16* __restrict__ oh,
                                                     __nv_bfloat16* __restrict__ om,
                                                     __nv_bfloat16* __restrict__ ol,
                                                     int n4) {
    int i = blockIdx.x * 256 + threadIdx.x;
    if (i < n4) {
        float4 v = reinterpret_cast<const float4*>(in)[i];
        __nv_bfloat16 h[4], m[4], l[4];
        split3(v.x, h[0], m[0], l[0]);
        split3(v.y, h[1], m[1], l[1]);
        split3(v.z, h[2], m[2], l[2]);
        split3(v.w, h[3], m[3], l[3]);
        reinterpret_cast<__nv_bfloat162*>(oh)[i * 2]     = __nv_bfloat162{h[0], h[1]};
        reinterpret_cast<__nv_bfloat162*>(oh)[i * 2 + 1] = __nv_bfloat162{h[2], h[3]};
        reinterpret_cast<__nv_bfloat162*>(om)[i * 2]     = __nv_bfloat162{m[0], m[1]};
        reinterpret_cast<__nv_bfloat162*>(om)[i * 2 + 1] = __nv_bfloat162{m[2], m[3]};
        reinterpret_cast<__nv_bfloat162*>(ol)[i * 2]     = __nv_bfloat162{l[0], l[1]};
        reinterpret_cast<__nv_bfloat162*>(ol)[i * 2 + 1] = __nv_bfloat162{l[2], l[3]};
    }
}

// W [h][k] row-major -> planes wt[k][h] = W[h][k]
__global__ __launch_bounds__(256) void splitWT_kernel(const float* __restrict__ W,
                                                      __nv_bfloat16* __restrict__ oh,
                                                      __nv_bfloat16* __restrict__ om,
                                                      __nv_bfloat16* __restrict__ ol) {
    __shared__ float tile[32][33];
    const int tx = threadIdx.x & 31;
    const int ty = threadIdx.x >> 5;
    const int k0 = blockIdx.x * 32;
    const int h0 = blockIdx.y * 32;
    #pragma unroll
    for (int j = 0; j < 32; j += 8)
        tile[ty + j][tx] = W[(size_t)(h0 + ty + j) * HID + k0 + tx];
    __syncthreads();
    #pragma unroll
    for (int j = 0; j < 32; j += 8) {
        float a = tile[tx][ty + j];
        __nv_bfloat16 h, m, l;
        split3(a, h, m, l);
        size_t o = (size_t)(k0 + ty + j) * HID + h0 + tx;
        oh[o] = h; om[o] = m; ol[o] = l;
    }
}

// ---------------------------------------------------------------------------
// c[i] = out_state[i] . b
// ---------------------------------------------------------------------------
__global__ __launch_bounds__(256) void dot_bias_kernel(const float* __restrict__ A,
                                                       const float* __restrict__ b) {
    const int i = blockIdx.x;
    const float* row = A + (size_t)i * HID;
    float s = 0.f;
    for (int h = threadIdx.x * 4; h < HID; h += 256 * 4) {
        float4 x = *reinterpret_cast<const float4*>(row + h);
        float4 y = *reinterpret_cast<const float4*>(b + h);
        s += x.x * y.x + x.y * y.y + x.z * y.z + x.w * y.w;
    }
    __shared__ float red[8];
    #pragma unroll
    for (int o = 16; o; o >>= 1) s += __shfl_xor_sync(0xffffffffu, s, o);
    if ((threadIdx.x & 31) == 0) red[threadIdx.x >> 5] = s;
    __syncthreads();
    if (threadIdx.x == 0) {
        float t = 0.f;
        #pragma unroll
        for (int k = 0; k < 8; k++) t += red[k];
        g_c[i] = t;
    }
}

// ---------------------------------------------------------------------------
// HMMA emulated-fp32 GEMM: C[M,N] = A[M,K] @ B[N,K]^T  (3-plane bf16 splits)
// Products kept: pa+pb <= 2  (hh, hm, mh, hl, lh, mm)
// Tile 128x128, 8 warps (2M x 4N), warp tile 64x32, K-chunk 32, 3-stage cp.async.
//   EPI=0: split C into bf16 h/m/l planes   EPI=1: C_f32 = C + bias[row]
// ---------------------------------------------------------------------------
constexpr int KC      = 32;              // k elems per chunk
constexpr int NC      = KDIM / KC;       // 64 chunks
constexpr int ROWB    = 80;              // padded row bytes (64B data + 16B pad)
constexpr int PLANE_B = 128 * ROWB;      // 10240
constexpr int STAGE_B = 6 * PLANE_B;     // 61440
constexpr int NSTAGE  = 3;
constexpr size_t SMEM_TOTAL = (size_t)NSTAGE * STAGE_B;   // 184320

template <int EPI>
__global__ __launch_bounds__(256, 1)
void gemm_mma(const __nv_bfloat16* __restrict__ Ah, const __nv_bfloat16* __restrict__ Am,
              const __nv_bfloat16* __restrict__ Al, const __nv_bfloat16* __restrict__ Bh,
              const __nv_bfloat16* __restrict__ Bm, const __nv_bfloat16* __restrict__ Bl,
              float* __restrict__ outF, __nv_bfloat16* __restrict__ Oh,
              __nv_bfloat16* __restrict__ Om, __nv_bfloat16* __restrict__ Ol,
              const float* __restrict__ bias, int N) {
    extern __shared__ char smem[];
    const uint32_t sb = smem_to_u32(smem);
    const int tid  = threadIdx.x;
    const int lane = tid & 31;
    const int w    = tid >> 5;
    const int wm   = w & 1;        // 2 warps along M
    const int wn   = w >> 1;       // 4 warps along N
    const int rowBase = blockIdx.y * 128;
    const int colBase = blockIdx.x * 128;

    const __nv_bfloat16* planes[6] = {Ah, Am, Al, Bh, Bm, Bl};

    // ldmatrix per-lane row offsets (constant across k-chunks)
    uint32_t aOff[4], bOff[2];
    #pragma unroll
    for (int mt = 0; mt < 4; mt++)
        aOff[mt] = (uint32_t)((wm * 64 + mt * 16 + (lane & 15)) * ROWB + ((lane >> 4) << 4));
    #pragma unroll
    for (int nb = 0; nb < 2; nb++)
        bOff[nb] = (uint32_t)((wn * 32 + nb * 16 + (lane & 7) + ((lane >> 4) << 3)) * ROWB
                              + (((lane >> 3) & 1) << 4));

    float acc[4][4][4];
    #pragma unroll
    for (int mt = 0; mt < 4; mt++)
        #pragma unroll
        for (int nt = 0; nt < 4; nt++)
            #pragma unroll
            for (int q = 0; q < 4; q++) acc[mt][nt][q] = 0.f;

    // cp.async stage loader: thread does 2 chunks of 16B per plane (12 total)
    const int lr = tid >> 2;        // 0..63
    const int lc = tid & 3;         // 0..3 (16B chunk within 64B row)
    auto load_stage = [&](int kc) {
        const uint32_t dstStage = sb + (uint32_t)(kc % NSTAGE) * STAGE_B;
        #pragma unroll
        for (int p = 0; p < 6; p++) {
            const int gbase = (p < 3 ? rowBase : colBase);
            #pragma unroll
            for (int j = 0; j < 2; j++) {
                const int r = lr + j * 64;
                const char* src = (const char*)(planes[p] + (size_t)(gbase + r) * KDIM
                                                + kc * KC) + lc * 16;
                cp16(dstStage + (uint32_t)(p * PLANE_B + r * ROWB + lc * 16), src);
            }
        }
    };

    // prologue
    #pragma unroll
    for (int kc = 0; kc < NSTAGE; kc++) { load_stage(kc); cp_commit(); }

    for (int kc = 0; kc < NC; kc++) {
        cp_wait<NSTAGE - 1>();
        __syncthreads();

        const uint32_t base = sb + (uint32_t)(kc % NSTAGE) * STAGE_B;
        #pragma unroll
        for (int s = 0; s < 2; s++) {       // two k16 steps per chunk
            uint32_t af[3][4][4];
            #pragma unroll
            for (int a = 0; a < 3; a++)
                #pragma unroll
                for (int mt = 0; mt < 4; mt++)
                    ldm4(af[a][mt], base + (uint32_t)(a * PLANE_B) + aOff[mt] + s * 32);
            #pragma unroll
            for (int pb = 0; pb < 3; pb++) {
                uint32_t bf[2][4];
                #pragma unroll
                for (int nb = 0; nb < 2; nb++)
                    ldm4(bf[nb], base + (uint32_t)((3 + pb) * PLANE_B) + bOff[nb] + s * 32);
                #pragma unroll
                for (int pa = 0; pa < 3; pa++) {
                    if (pa + pb > 2) continue;     // 6 kept products
                    #pragma unroll
                    for (int mt = 0; mt < 4; mt++)
                        #pragma unroll
                        for (int nt = 0; nt < 4; nt++)
                            mma16816(acc[mt][nt], af[pa][mt], &bf[nt >> 1][(nt & 1) * 2]);
                }
            }
        }

        __syncthreads();
        if (kc + NSTAGE < NC) load_stage(kc + NSTAGE);
        cp_commit();
    }

    // epilogue
    const int g   = lane >> 2;
    const int tig = lane & 3;
    #pragma unroll
    for (int mt = 0; mt < 4; mt++) {
        #pragma unroll
        for (int hh = 0; hh < 2; hh++) {
            const int row = rowBase + wm * 64 + mt * 16 + g + hh * 8;
            const float rb = (EPI == 1) ? bias[row] : 0.f;
            #pragma unroll
            for (int nt = 0; nt < 4; nt++) {
                const int col = colBase + wn * 32 + nt * 8 + tig * 2;
                const float v0 = acc[mt][nt][hh * 2];
                const float v1 = acc[mt][nt][hh * 2 + 1];
                if (EPI == 0) {
                    __nv_bfloat16 h0, m0, l0, h1, m1, l1;
                    split3(v0, h0, m0, l0);
                    split3(v1, h1, m1, l1);
                    const size_t o = (size_t)row * N + col;
                    *reinterpret_cast<__nv_bfloat162*>(Oh + o) = __nv_bfloat162{h0, h1};
                    *reinterpret_cast<__nv_bfloat162*>(Om + o) = __nv_bfloat162{m0, m1};
                    *reinterpret_cast<__nv_bfloat162*>(Ol + o) = __nv_bfloat162{l0, l1};
                } else {
                    *reinterpret_cast<float2*>(outF + (size_t)row * N + col) =
                        make_float2(v0 + rb, v1 + rb);
                }
            }
        }
    }
}

// ---------------------------------------------------------------------------
// Row softmax over 4096 columns
// ---------------------------------------------------------------------------
__global__ __launch_bounds__(256) void softmax_kernel(const float* __restrict__ scores,
                                                      float* __restrict__ out) {
    const int i = blockIdx.x;
    const float4* row = reinterpret_cast<const float4*>(scores + (size_t)i * SEQ);
    float4* orow = reinterpret_cast<float4*>(out + (size_t)i * SEQ);

    float4 v[4];
    float m = -1e30f;
    #pragma unroll
    for (int t = 0; t < 4; t++) {
        v[t] = row[threadIdx.x + t * 256];
        m = fmaxf(m, fmaxf(fmaxf(v[t].x, v[t].y), fmaxf(v[t].z, v[t].w)));
    }
    __shared__ float red[8];
    #pragma unroll
    for (int o = 16; o; o >>= 1) m = fmaxf(m, __shfl_xor_sync(0xffffffffu, m, o));
    if ((threadIdx.x & 31) == 0) red[threadIdx.x >> 5] = m;
    __syncthreads();
    float m_all = red[0];
    #pragma unroll
    for (int k = 1; k < 8; k++) m_all = fmaxf(m_all, red[k]);
    __syncthreads();

    float s = 0.f;
    #pragma unroll
    for (int t = 0; t < 4; t++) {
        v[t].x = __expf(v[t].x - m_all);
        v[t].y = __expf(v[t].y - m_all);
        v[t].z = __expf(v[t].z - m_all);
        v[t].w = __expf(v[t].w - m_all);
        s += v[t].x + v[t].y + v[t].z + v[t].w;
    }
    #pragma unroll
    for (int o = 16; o; o >>= 1) s += __shfl_xor_sync(0xffffffffu, s, o);
    if ((threadIdx.x & 31) == 0) red[threadIdx.x >> 5] = s;
    __syncthreads();
    float s_all = 0.f;
    #pragma unroll
    for (int k = 0; k < 8; k++) s_all += red[k];
    const float inv = 1.0f / s_all;

    #pragma unroll
    for (int t = 0; t < 4; t++) {
        float4 o4 = make_float4(v[t].x * inv, v[t].y * inv, v[t].z * inv, v[t].w * inv);
        orow[threadIdx.x + t * 256] = o4;
    }
}

// ---------------------------------------------------------------------------
extern "C" void kernel_launch(void* const* d_in, const int* in_sizes, int n_in,
                              void* d_out, int out_size) {
    const float* out_state = (const float*)d_in[0];  // [2048, 2048]
    const float* history   = (const float*)d_in[1];  // [4096, 2048]
    const float* W         = (const float*)d_in[2];  // [2048, 2048]
    const float* b         = (const float*)d_in[3];  // [2048]
    float* out = (float*)d_out;                      // [2048, 4096]

    __nv_bfloat16 *osH, *osM, *osL, *wtH, *wtM, *wtL, *hiH, *hiM, *hiL, *tH, *tM, *tL;
    float *scores, *cvec;
    cudaGetSymbolAddress((void**)&osH, g_osH); cudaGetSymbolAddress((void**)&osM, g_osM);
    cudaGetSymbolAddress((void**)&osL, g_osL);
    cudaGetSymbolAddress((void**)&wtH, g_wtH); cudaGetSymbolAddress((void**)&wtM, g_wtM);
    cudaGetSymbolAddress((void**)&wtL, g_wtL);
    cudaGetSymbolAddress((void**)&hiH, g_hiH); cudaGetSymbolAddress((void**)&hiM, g_hiM);
    cudaGetSymbolAddress((void**)&hiL, g_hiL);
    cudaGetSymbolAddress((void**)&tH, g_tH); cudaGetSymbolAddress((void**)&tM, g_tM);
    cudaGetSymbolAddress((void**)&tL, g_tL);
    cudaGetSymbolAddress((void**)&scores, g_scores);
    cudaGetSymbolAddress((void**)&cvec, g_c);

    cudaFuncSetAttribute(gemm_mma<0>, cudaFuncAttributeMaxDynamicSharedMemorySize,
                         (int)SMEM_TOTAL);
    cudaFuncSetAttribute(gemm_mma<1>, cudaFuncAttributeMaxDynamicSharedMemorySize,
                         (int)SMEM_TOTAL);

    // 1. splits (vectorized x4)
    split3_kernel<<<(S_LEN * HID / 4 + 255) / 256, 256>>>(out_state, osH, osM, osL,
                                                          S_LEN * HID / 4);
    split3_kernel<<<(SEQ * HID / 4 + 255) / 256, 256>>>(history, hiH, hiM, hiL,
                                                        SEQ * HID / 4);
    splitWT_kernel<<<dim3(HID / 32, HID / 32), 256>>>(W, wtH, wtM, wtL);

    // 2. c[i] = out_state[i] . b
    dot_bias_kernel<<<S_LEN, 256>>>(out_state, b);

    // 3. T = out_state @ W   (B operand = wt[k][h] planes), epilogue splits T
    gemm_mma<0><<<dim3(HID / 128, S_LEN / 128), 256, SMEM_TOTAL>>>(
        osH, osM, osL, wtH, wtM, wtL, nullptr, tH, tM, tL, nullptr, HID);

    // 4. scores = T @ history^T + c
    gemm_mma<1><<<dim3(SEQ / 128, S_LEN / 128), 256, SMEM_TOTAL>>>(
        tH, tM, tL, hiH, hiM, hiL, scores, nullptr, nullptr, nullptr, cvec, SEQ);

    // 5. softmax rows
    softmax_kernel<<<S_LEN, 256>>>(scores, out);
}

// round 4
// speedup vs baseline: 2.2311x; 1.6785x over previous
#include <cuda_runtime.h>
#include <cuda_fp16.h>
#include <cstdint>

constexpr int S_LEN = 2048;
constexpr int SEQ   = 4096;
constexpr int HID   = 2048;
constexpr int KDIM  = 2048;
constexpr float WSCALE = 64.0f;          // keep W's m-plane out of fp16 subnormals

// ---------------------------------------------------------------------------
// Scratch (__device__ globals; allocation-free rule)
// ---------------------------------------------------------------------------
__device__ __half g_osH[(size_t)S_LEN * HID];
__device__ __half g_osM[(size_t)S_LEN * HID];
__device__ __half g_wtH[(size_t)HID * HID];    // wt[r][c] = 64*W[c][r]  (W^T, scaled)
__device__ __half g_wtM[(size_t)HID * HID];
__device__ __half g_hiH[(size_t)SEQ * HID];
__device__ __half g_hiM[(size_t)SEQ * HID];
__device__ __half g_tH[(size_t)S_LEN * HID];   // planes of T' = 64*T
__device__ __half g_tM[(size_t)S_LEN * HID];
__device__ float g_scores[(size_t)S_LEN * SEQ];
__device__ float g_c[S_LEN];

// ---------------------------------------------------------------------------
// PTX helpers (sm_80-baseline features only: legal on .target sm_103)
// ---------------------------------------------------------------------------
__device__ __forceinline__ uint32_t smem_to_u32(const void* p) {
    uint32_t a;
    asm("{ .reg .u64 t; cvta.to.shared.u64 t, %1; cvt.u32.u64 %0, t; }" : "=r"(a) : "l"(p));
    return a;
}
__device__ __forceinline__ void cp16(uint32_t dst, const void* src) {
    asm volatile("cp.async.cg.shared.global [%0], [%1], 16;" :: "r"(dst), "l"(src));
}
__device__ __forceinline__ void cp_commit() {
    asm volatile("cp.async.commit_group;" ::: "memory");
}
template <int N>
__device__ __forceinline__ void cp_wait() {
    asm volatile("cp.async.wait_group %0;" :: "n"(N) : "memory");
}
__device__ __forceinline__ void ldm4(uint32_t* r, uint32_t addr) {
    asm volatile("ldmatrix.sync.aligned.m8n8.x4.shared.b16 {%0,%1,%2,%3}, [%4];"
                 : "=r"(r[0]), "=r"(r[1]), "=r"(r[2]), "=r"(r[3]) : "r"(addr));
}
__device__ __forceinline__ void mma16816(float* d, const uint32_t* a, const uint32_t* b) {
    asm volatile(
        "mma.sync.aligned.m16n8k16.row.col.f32.f16.f16.f32 "
        "{%0,%1,%2,%3}, {%4,%5,%6,%7}, {%8,%9}, {%0,%1,%2,%3};"
        : "+f"(d[0]), "+f"(d[1]), "+f"(d[2]), "+f"(d[3])
        : "r"(a[0]), "r"(a[1]), "r"(a[2]), "r"(a[3]), "r"(b[0]), "r"(b[1]));
}

// ---------------------------------------------------------------------------
// 2-way fp16 split helpers
// ---------------------------------------------------------------------------
__device__ __forceinline__ void split2(float a, __half& h, __half& m) {
    h = __float2half_rn(a);
    float r = a - __half2float(h);
    m = __float2half_rn(r);
}

__global__ __launch_bounds__(256) void split2_kernel(const float* __restrict__ in,
                                                     __half* __restrict__ oh,
                                                     __half* __restrict__ om,
                                                     int n4) {
    int i = blockIdx.x * 256 + threadIdx.x;
    if (i < n4) {
        float4 v = reinterpret_cast<const float4*>(in)[i];
        __half h[4], m[4];
        split2(v.x, h[0], m[0]);
        split2(v.y, h[1], m[1]);
        split2(v.z, h[2], m[2]);
        split2(v.w, h[3], m[3]);
        reinterpret_cast<__half2*>(oh)[i * 2]     = __half2{h[0], h[1]};
        reinterpret_cast<__half2*>(oh)[i * 2 + 1] = __half2{h[2], h[3]};
        reinterpret_cast<__half2*>(om)[i * 2]     = __half2{m[0], m[1]};
        reinterpret_cast<__half2*>(om)[i * 2 + 1] = __half2{m[2], m[3]};
    }
}

// W [h][k] row-major -> planes wt[k][h] = 64*W[h][k]   (transpose + scale)
__global__ __launch_bounds__(256) void splitWT_kernel(const float* __restrict__ W,
                                                      __half* __restrict__ oh,
                                                      __half* __restrict__ om) {
    __shared__ float tile[32][33];
    const int tx = threadIdx.x & 31;
    const int ty = threadIdx.x >> 5;
    const int k0 = blockIdx.x * 32;
    const int h0 = blockIdx.y * 32;
    #pragma unroll
    for (int j = 0; j < 32; j += 8)
        tile[ty + j][tx] = W[(size_t)(h0 + ty + j) * HID + k0 + tx];
    __syncthreads();
    #pragma unroll
    for (int j = 0; j < 32; j += 8) {
        float a = tile[tx][ty + j] * WSCALE;
        __half h, m;
        split2(a, h, m);
        size_t o = (size_t)(k0 + ty + j) * HID + h0 + tx;
        oh[o] = h; om[o] = m;
    }
}

// ---------------------------------------------------------------------------
// c[i] = out_state[i] . b
// ---------------------------------------------------------------------------
__global__ __launch_bounds__(256) void dot_bias_kernel(const float* __restrict__ A,
                                                       const float* __restrict__ b) {
    const int i = blockIdx.x;
    const float* row = A + (size_t)i * HID;
    float s = 0.f;
    for (int h = threadIdx.x * 4; h < HID; h += 256 * 4) {
        float4 x = *reinterpret_cast<const float4*>(row + h);
        float4 y = *reinterpret_cast<const float4*>(b + h);
        s += x.x * y.x + x.y * y.y + x.z * y.z + x.w * y.w;
    }
    __shared__ float red[8];
    #pragma unroll
    for (int o = 16; o; o >>= 1) s += __shfl_xor_sync(0xffffffffu, s, o);
    if ((threadIdx.x & 31) == 0) red[threadIdx.x >> 5] = s;
    __syncthreads();
    if (threadIdx.x == 0) {
        float t = 0.f;
        #pragma unroll
        for (int k = 0; k < 8; k++) t += red[k];
        g_c[i] = t;
    }
}

// ---------------------------------------------------------------------------
// HMMA emulated-fp32 GEMM: C[M,N] = A[M,K] @ B[N,K]^T  (2-plane fp16 splits)
// Products kept: hh, hm, mh  (pa+pb <= 1)
// Tile 128x128, 8 warps (2M x 4N), warp tile 64x32, K-chunk 32, 4-stage cp.async.
//   EPI=0: split C into fp16 h/m planes   EPI=1: C_f32 = C*(1/WSCALE) + bias[row]
// ---------------------------------------------------------------------------
constexpr int KC      = 32;
constexpr int NC      = KDIM / KC;       // 64 chunks
constexpr int ROWB    = 80;              // 64B data + 16B pad
constexpr int PLANE_B = 128 * ROWB;      // 10240
constexpr int STAGE_B = 4 * PLANE_B;     // 40960 (4 planes: Ah, Am, Bh, Bm)
constexpr int NSTAGE  = 4;
constexpr size_t SMEM_TOTAL = (size_t)NSTAGE * STAGE_B;   // 163840

template <int EPI>
__global__ __launch_bounds__(256, 1)
void gemm_mma(const __half* __restrict__ Ah, const __half* __restrict__ Am,
              const __half* __restrict__ Bh, const __half* __restrict__ Bm,
              float* __restrict__ outF, __half* __restrict__ Oh,
              __half* __restrict__ Om, const float* __restrict__ bias, int N) {
    extern __shared__ char smem[];
    const uint32_t sb = smem_to_u32(smem);
    const int tid  = threadIdx.x;
    const int lane = tid & 31;
    const int w    = tid >> 5;
    const int wm   = w & 1;
    const int wn   = w >> 1;
    const int rowBase = blockIdx.y * 128;
    const int colBase = blockIdx.x * 128;

    const __half* planes[4] = {Ah, Am, Bh, Bm};

    uint32_t aOff[4], bOff[2];
    #pragma unroll
    for (int mt = 0; mt < 4; mt++)
        aOff[mt] = (uint32_t)((wm * 64 + mt * 16 + (lane & 15)) * ROWB + ((lane >> 4) << 4));
    #pragma unroll
    for (int nb = 0; nb < 2; nb++)
        bOff[nb] = (uint32_t)((wn * 32 + nb * 16 + (lane & 7) + ((lane >> 4) << 3)) * ROWB
                              + (((lane >> 3) & 1) << 4));

    float acc[4][4][4];
    #pragma unroll
    for (int mt = 0; mt < 4; mt++)
        #pragma unroll
        for (int nt = 0; nt < 4; nt++)
            #pragma unroll
            for (int q = 0; q < 4; q++) acc[mt][nt][q] = 0.f;

    const int lr = tid >> 2;        // 0..63
    const int lc = tid & 3;         // 16B chunk within 64B row
    auto load_stage = [&](int kc) {
        const uint32_t dstStage = sb + (uint32_t)(kc % NSTAGE) * STAGE_B;
        #pragma unroll
        for (int p = 0; p < 4; p++) {
            const int gbase = (p < 2 ? rowBase : colBase);
            #pragma unroll
            for (int j = 0; j < 2; j++) {
                const int r = lr + j * 64;
                const char* src = (const char*)(planes[p] + (size_t)(gbase + r) * KDIM
                                                + kc * KC) + lc * 16;
                cp16(dstStage + (uint32_t)(p * PLANE_B + r * ROWB + lc * 16), src);
            }
        }
    };

    #pragma unroll
    for (int kc = 0; kc < NSTAGE; kc++) { load_stage(kc); cp_commit(); }

    for (int kc = 0; kc < NC; kc++) {
        cp_wait<NSTAGE - 1>();
        __syncthreads();

        const uint32_t base = sb + (uint32_t)(kc % NSTAGE) * STAGE_B;
        #pragma unroll
        for (int s = 0; s < 2; s++) {
            uint32_t af[2][4][4];
            #pragma unroll
            for (int pa = 0; pa < 2; pa++)
                #pragma unroll
                for (int mt = 0; mt < 4; mt++)
                    ldm4(af[pa][mt], base + (uint32_t)(pa * PLANE_B) + aOff[mt] + s * 32);
            #pragma unroll
            for (int pb = 0; pb < 2; pb++) {
                uint32_t bf[2][4];
                #pragma unroll
                for (int nb = 0; nb < 2; nb++)
                    ldm4(bf[nb], base + (uint32_t)((2 + pb) * PLANE_B) + bOff[nb] + s * 32);
                #pragma unroll
                for (int pa = 0; pa < 2; pa++) {
                    if (pa + pb > 1) continue;   // hh, hm, mh
                    #pragma unroll
                    for (int mt = 0; mt < 4; mt++)
                        #pragma unroll
                        for (int nt = 0; nt < 4; nt++)
                            mma16816(acc[mt][nt], af[pa][mt], &bf[nt >> 1][(nt & 1) * 2]);
                }
            }
        }

        __syncthreads();
        if (kc + NSTAGE < NC) load_stage(kc + NSTAGE);
        cp_commit();
    }

    const int g   = lane >> 2;
    const int tig = lane & 3;
    constexpr float INVS = 1.0f / WSCALE;
    #pragma unroll
    for (int mt = 0; mt < 4; mt++) {
        #pragma unroll
        for (int hh = 0; hh < 2; hh++) {
            const int row = rowBase + wm * 64 + mt * 16 + g + hh * 8;
            const float rb = (EPI == 1) ? bias[row] : 0.f;
            #pragma unroll
            for (int nt = 0; nt < 4; nt++) {
                const int col = colBase + wn * 32 + nt * 8 + tig * 2;
                const float v0 = acc[mt][nt][hh * 2];
                const float v1 = acc[mt][nt][hh * 2 + 1];
                if (EPI == 0) {
                    __half h0, m0, h1, m1;
                    split2(v0, h0, m0);
                    split2(v1, h1, m1);
                    const size_t o = (size_t)row * N + col;
                    *reinterpret_cast<__half2*>(Oh + o) = __half2{h0, h1};
                    *reinterpret_cast<__half2*>(Om + o) = __half2{m0, m1};
                } else {
                    *reinterpret_cast<float2*>(outF + (size_t)row * N + col) =
                        make_float2(fmaf(v0, INVS, rb), fmaf(v1, INVS, rb));
                }
            }
        }
    }
}

// ---------------------------------------------------------------------------
// Row softmax over 4096 columns
// ---------------------------------------------------------------------------
__global__ __launch_bounds__(256) void softmax_kernel(const float* __restrict__ scores,
                                                      float* __restrict__ out) {
    const int i = blockIdx.x;
    const float4* row = reinterpret_cast<const float4*>(scores + (size_t)i * SEQ);
    float4* orow = reinterpret_cast<float4*>(out + (size_t)i * SEQ);

    float4 v[4];
    float m = -1e30f;
    #pragma unroll
    for (int t = 0; t < 4; t++) {
        v[t] = row[threadIdx.x + t * 256];
        m = fmaxf(m, fmaxf(fmaxf(v[t].x, v[t].y), fmaxf(v[t].z, v[t].w)));
    }
    __shared__ float red[8];
    #pragma unroll
    for (int o = 16; o; o >>= 1) m = fmaxf(m, __shfl_xor_sync(0xffffffffu, m, o));
    if ((threadIdx.x & 31) == 0) red[threadIdx.x >> 5] = m;
    __syncthreads();
    float m_all = red[0];
    #pragma unroll
    for (int k = 1; k < 8; k++) m_all = fmaxf(m_all, red[k]);
    __syncthreads();

    float s = 0.f;
    #pragma unroll
    for (int t = 0; t < 4; t++) {
        v[t].x = __expf(v[t].x - m_all);
        v[t].y = __expf(v[t].y - m_all);
        v[t].z = __expf(v[t].z - m_all);
        v[t].w = __expf(v[t].w - m_all);
        s += v[t].x + v[t].y + v[t].z + v[t].w;
    }
    #pragma unroll
    for (int o = 16; o; o >>= 1) s += __shfl_xor_sync(0xffffffffu, s, o);
    if ((threadIdx.x & 31) == 0) red[threadIdx.x >> 5] = s;
    __syncthreads();
    float s_all = 0.f;
    #pragma unroll
    for (int k = 0; k < 8; k++) s_all += red[k];
    const float inv = 1.0f / s_all;

    #pragma unroll
    for (int t = 0; t < 4; t++) {
        float4 o4 = make_float4(v[t].x * inv, v[t].y * inv, v[t].z * inv, v[t].w * inv);
        orow[threadIdx.x + t * 256] = o4;
    }
}

// ---------------------------------------------------------------------------
extern "C" void kernel_launch(void* const* d_in, const int* in_sizes, int n_in,
                              void* d_out, int out_size) {
    const float* out_state = (const float*)d_in[0];  // [2048, 2048]
    const float* history   = (const float*)d_in[1];  // [4096, 2048]
    const float* W         = (const float*)d_in[2];  // [2048, 2048]
    const float* b         = (const float*)d_in[3];  // [2048]
    float* out = (float*)d_out;                      // [2048, 4096]

    __half *osH, *osM, *wtH, *wtM, *hiH, *hiM, *tH, *tM;
    float *scores, *cvec;
    cudaGetSymbolAddress((void**)&osH, g_osH); cudaGetSymbolAddress((void**)&osM, g_osM);
    cudaGetSymbolAddress((void**)&wtH, g_wtH); cudaGetSymbolAddress((void**)&wtM, g_wtM);
    cudaGetSymbolAddress((void**)&hiH, g_hiH); cudaGetSymbolAddress((void**)&hiM, g_hiM);
    cudaGetSymbolAddress((void**)&tH, g_tH);   cudaGetSymbolAddress((void**)&tM, g_tM);
    cudaGetSymbolAddress((void**)&scores, g_scores);
    cudaGetSymbolAddress((void**)&cvec, g_c);

    cudaFuncSetAttribute(gemm_mma<0>, cudaFuncAttributeMaxDynamicSharedMemorySize,
                         (int)SMEM_TOTAL);
    cudaFuncSetAttribute(gemm_mma<1>, cudaFuncAttributeMaxDynamicSharedMemorySize,
                         (int)SMEM_TOTAL);

    // 1. splits
    split2_kernel<<<(S_LEN * HID / 4 + 255) / 256, 256>>>(out_state, osH, osM,
                                                          S_LEN * HID / 4);
    split2_kernel<<<(SEQ * HID / 4 + 255) / 256, 256>>>(history, hiH, hiM,
                                                        SEQ * HID / 4);
    splitWT_kernel<<<dim3(HID / 32, HID / 32), 256>>>(W, wtH, wtM);

    // 2. c[i] = out_state[i] . b
    dot_bias_kernel<<<S_LEN, 256>>>(out_state, b);

    // 3. T' = out_state @ (64*W); epilogue splits T' into fp16 planes
    gemm_mma<0><<<dim3(HID / 128, S_LEN / 128), 256, SMEM_TOTAL>>>(
        osH, osM, wtH, wtM, nullptr, tH, tM, nullptr, HID);

    // 4. scores = (T' @ history^T)/64 + c
    gemm_mma<1><<<dim3(SEQ / 128, S_LEN / 128), 256, SMEM_TOTAL>>>(
        tH, tM, hiH, hiM, scores, nullptr, nullptr, cvec, SEQ);

    // 5. softmax rows
    softmax_kernel<<<S_LEN, 256>>>(scores, out);
}

// round 5
// speedup vs baseline: 2.5188x; 1.1289x over previous
#include <cuda_runtime.h>
#include <cuda_fp16.h>
#include <cstdint>

constexpr int S_LEN = 2048;
constexpr int SEQ   = 4096;
constexpr int HID   = 2048;
constexpr int KDIM  = 2048;
constexpr float WSCALE = 64.0f;          // keep W's m-plane out of fp16 subnormals

// ---------------------------------------------------------------------------
// Scratch (__device__ globals; allocation-free rule)
// ---------------------------------------------------------------------------
__device__ __half g_osH[(size_t)S_LEN * HID];
__device__ __half g_osM[(size_t)S_LEN * HID];
__device__ __half g_wtH[(size_t)HID * HID];    // wt[k][h] = 64*W[h][k]
__device__ __half g_wtM[(size_t)HID * HID];
__device__ __half g_hiH[(size_t)SEQ * HID];
__device__ __half g_hiM[(size_t)SEQ * HID];
__device__ __half g_tH[(size_t)S_LEN * HID];   // planes of T' = 64*T
__device__ __half g_tM[(size_t)S_LEN * HID];
__device__ float g_scores[(size_t)S_LEN * SEQ];
__device__ float g_c[S_LEN];

// ---------------------------------------------------------------------------
// PTX helpers (sm_80-baseline features only: legal on .target sm_103)
// ---------------------------------------------------------------------------
__device__ __forceinline__ uint32_t smem_to_u32(const void* p) {
    uint32_t a;
    asm("{ .reg .u64 t; cvta.to.shared.u64 t, %1; cvt.u32.u64 %0, t; }" : "=r"(a) : "l"(p));
    return a;
}
__device__ __forceinline__ void cp16(uint32_t dst, const void* src) {
    asm volatile("cp.async.cg.shared.global [%0], [%1], 16;" :: "r"(dst), "l"(src));
}
__device__ __forceinline__ void cp_commit() {
    asm volatile("cp.async.commit_group;" ::: "memory");
}
template <int N>
__device__ __forceinline__ void cp_wait() {
    asm volatile("cp.async.wait_group %0;" :: "n"(N) : "memory");
}
__device__ __forceinline__ void ldm4(uint32_t* r, uint32_t addr) {
    asm volatile("ldmatrix.sync.aligned.m8n8.x4.shared.b16 {%0,%1,%2,%3}, [%4];"
                 : "=r"(r[0]), "=r"(r[1]), "=r"(r[2]), "=r"(r[3]) : "r"(addr));
}
__device__ __forceinline__ void mma16816(float* d, const uint32_t* a, const uint32_t* b) {
    asm volatile(
        "mma.sync.aligned.m16n8k16.row.col.f32.f16.f16.f32 "
        "{%0,%1,%2,%3}, {%4,%5,%6,%7}, {%8,%9}, {%0,%1,%2,%3};"
        : "+f"(d[0]), "+f"(d[1]), "+f"(d[2]), "+f"(d[3])
        : "r"(a[0]), "r"(a[1]), "r"(a[2]), "r"(a[3]), "r"(b[0]), "r"(b[1]));
}

// ---------------------------------------------------------------------------
// 2-way fp16 split helpers
// ---------------------------------------------------------------------------
__device__ __forceinline__ void split2(float a, __half& h, __half& m) {
    h = __float2half_rn(a);
    float r = a - __half2float(h);
    m = __float2half_rn(r);
}

__global__ __launch_bounds__(256) void split2_kernel(const float* __restrict__ in,
                                                     __half* __restrict__ oh,
                                                     __half* __restrict__ om,
                                                     int n4) {
    int i = blockIdx.x * 256 + threadIdx.x;
    if (i < n4) {
        float4 v = reinterpret_cast<const float4*>(in)[i];
        __half h[4], m[4];
        split2(v.x, h[0], m[0]);
        split2(v.y, h[1], m[1]);
        split2(v.z, h[2], m[2]);
        split2(v.w, h[3], m[3]);
        reinterpret_cast<__half2*>(oh)[i * 2]     = __half2{h[0], h[1]};
        reinterpret_cast<__half2*>(oh)[i * 2 + 1] = __half2{h[2], h[3]};
        reinterpret_cast<__half2*>(om)[i * 2]     = __half2{m[0], m[1]};
        reinterpret_cast<__half2*>(om)[i * 2 + 1] = __half2{m[2], m[3]};
    }
}

// W [h][k] row-major -> planes wt[k][h] = 64*W[h][k]   (transpose + scale)
__global__ __launch_bounds__(256) void splitWT_kernel(const float* __restrict__ W,
                                                      __half* __restrict__ oh,
                                                      __half* __restrict__ om) {
    __shared__ float tile[32][33];
    const int tx = threadIdx.x & 31;
    const int ty = threadIdx.x >> 5;
    const int k0 = blockIdx.x * 32;
    const int h0 = blockIdx.y * 32;
    #pragma unroll
    for (int j = 0; j < 32; j += 8)
        tile[ty + j][tx] = W[(size_t)(h0 + ty + j) * HID + k0 + tx];
    __syncthreads();
    #pragma unroll
    for (int j = 0; j < 32; j += 8) {
        float a = tile[tx][ty + j] * WSCALE;
        __half h, m;
        split2(a, h, m);
        size_t o = (size_t)(k0 + ty + j) * HID + h0 + tx;
        oh[o] = h; om[o] = m;
    }
}

// ---------------------------------------------------------------------------
// c[i] = out_state[i] . b
// ---------------------------------------------------------------------------
__global__ __launch_bounds__(256) void dot_bias_kernel(const float* __restrict__ A,
                                                       const float* __restrict__ b) {
    const int i = blockIdx.x;
    const float* row = A + (size_t)i * HID;
    float s = 0.f;
    for (int h = threadIdx.x * 4; h < HID; h += 256 * 4) {
        float4 x = *reinterpret_cast<const float4*>(row + h);
        float4 y = *reinterpret_cast<const float4*>(b + h);
        s += x.x * y.x + x.y * y.y + x.z * y.z + x.w * y.w;
    }
    __shared__ float red[8];
    #pragma unroll
    for (int o = 16; o; o >>= 1) s += __shfl_xor_sync(0xffffffffu, s, o);
    if ((threadIdx.x & 31) == 0) red[threadIdx.x >> 5] = s;
    __syncthreads();
    if (threadIdx.x == 0) {
        float t = 0.f;
        #pragma unroll
        for (int k = 0; k < 8; k++) t += red[k];
        g_c[i] = t;
    }
}

// ---------------------------------------------------------------------------
// HMMA emulated-fp32 GEMM: C[M,N] = A[M,K] @ B[N,K]^T  (2-plane fp16 splits)
// Products: hh, hm, mh.  CTA tile 128x256, 8 warps (2M x 4N), warp tile 64x64.
// K-chunk 32, 3-stage cp.async.
//   EPI=0: split C into fp16 h/m planes   EPI=1: C_f32 = C*(1/WSCALE) + bias[row]
// ---------------------------------------------------------------------------
constexpr int NTILE   = 256;
constexpr int KC      = 32;
constexpr int NC      = KDIM / KC;             // 64 chunks
constexpr int ROWB    = 80;                    // 64B data + 16B pad
constexpr int R_TOT   = 2 * (128 + NTILE);     // 768 rows per stage
constexpr int STAGE_B = R_TOT * ROWB;          // 61440
constexpr int NSTAGE  = 3;
constexpr size_t SMEM_TOTAL = (size_t)NSTAGE * STAGE_B;   // 184320
// plane row offsets within a stage
constexpr int PL_A0 = 0;            // Ah rows [0,128)
constexpr int PL_A1 = 128;          // Am
constexpr int PL_B0 = 256;          // Bh rows [0,NTILE)
constexpr int PL_B1 = 256 + NTILE;  // Bm

template <int EPI>
__global__ __launch_bounds__(256, 1)
void gemm_mma(const __half* __restrict__ Ah, const __half* __restrict__ Am,
              const __half* __restrict__ Bh, const __half* __restrict__ Bm,
              float* __restrict__ outF, __half* __restrict__ Oh,
              __half* __restrict__ Om, const float* __restrict__ bias, int N) {
    extern __shared__ char smem[];
    const uint32_t sb = smem_to_u32(smem);
    const int tid  = threadIdx.x;
    const int lane = tid & 31;
    const int w    = tid >> 5;
    const int wm   = w & 1;        // 2 warps along M (64 rows each)
    const int wn   = w >> 1;       // 4 warps along N (64 cols each)
    const int rowBase = blockIdx.y * 128;
    const int colBase = blockIdx.x * NTILE;

    // ldmatrix per-lane offsets
    uint32_t aOff[4], bOff[4];
    #pragma unroll
    for (int mt = 0; mt < 4; mt++)
        aOff[mt] = (uint32_t)((wm * 64 + mt * 16 + (lane & 15)) * ROWB + ((lane >> 4) << 4));
    #pragma unroll
    for (int nb = 0; nb < 4; nb++)
        bOff[nb] = (uint32_t)((wn * 64 + nb * 16 + (lane & 7) + ((lane >> 4) << 3)) * ROWB
                              + (((lane >> 3) & 1) << 4));

    float acc[4][8][4];
    #pragma unroll
    for (int mt = 0; mt < 4; mt++)
        #pragma unroll
        for (int nt = 0; nt < 8; nt++)
            #pragma unroll
            for (int q = 0; q < 4; q++) acc[mt][nt][q] = 0.f;

    const int lr = tid >> 2;        // 0..63
    const int lc = tid & 3;         // 16B chunk within 64B row
    auto load_stage = [&](int kc) {
        const uint32_t dstStage = sb + (uint32_t)(kc % NSTAGE) * STAGE_B;
        const char* srcA[2] = {(const char*)(Ah + (size_t)(rowBase + lr) * KDIM + kc * KC),
                               (const char*)(Am + (size_t)(rowBase + lr) * KDIM + kc * KC)};
        const char* srcB[2] = {(const char*)(Bh + (size_t)(colBase + lr) * KDIM + kc * KC),
                               (const char*)(Bm + (size_t)(colBase + lr) * KDIM + kc * KC)};
        #pragma unroll
        for (int p = 0; p < 2; p++) {
            #pragma unroll
            for (int j = 0; j < 2; j++) {   // A rows: lr, lr+64
                const int r = lr + j * 64;
                cp16(dstStage + (uint32_t)((PL_A0 + p * 128 + r) * ROWB + lc * 16),
                     srcA[p] + (size_t)j * 64 * KDIM * 2 + lc * 16);
            }
            #pragma unroll
            for (int j = 0; j < NTILE / 64; j++) {   // B rows: lr + j*64
                const int r = lr + j * 64;
                cp16(dstStage + (uint32_t)((PL_B0 + p * NTILE + r) * ROWB + lc * 16),
                     srcB[p] + (size_t)j * 64 * KDIM * 2 + lc * 16);
            }
        }
    };

    #pragma unroll
    for (int kc = 0; kc < NSTAGE; kc++) { load_stage(kc); cp_commit(); }

    for (int kc = 0; kc < NC; kc++) {
        cp_wait<NSTAGE - 1>();
        __syncthreads();

        const uint32_t base = sb + (uint32_t)(kc % NSTAGE) * STAGE_B;
        #pragma unroll
        for (int s = 0; s < 2; s++) {               // two k16 steps per chunk
            uint32_t af[2][4][4];
            #pragma unroll
            for (int pa = 0; pa < 2; pa++)
                #pragma unroll
                for (int mt = 0; mt < 4; mt++)
                    ldm4(af[pa][mt],
                         base + (uint32_t)((PL_A0 + pa * 128) * ROWB) + aOff[mt] + s * 32);
            #pragma unroll
            for (int pb = 0; pb < 2; pb++) {
                uint32_t bf[4][4];
                #pragma unroll
                for (int nb = 0; nb < 4; nb++)
                    ldm4(bf[nb],
                         base + (uint32_t)((PL_B0 + pb * NTILE) * ROWB) + bOff[nb] + s * 32);
                #pragma unroll
                for (int pa = 0; pa < 2; pa++) {
                    if (pa + pb > 1) continue;      // hh, hm, mh
                    #pragma unroll
                    for (int mt = 0; mt < 4; mt++)
                        #pragma unroll
                        for (int nt = 0; nt < 8; nt++)
                            mma16816(acc[mt][nt], af[pa][mt], &bf[nt >> 1][(nt & 1) * 2]);
                }
            }
        }

        __syncthreads();
        if (kc + NSTAGE < NC) load_stage(kc + NSTAGE);
        cp_commit();
    }

    const int g   = lane >> 2;
    const int tig = lane & 3;
    constexpr float INVS = 1.0f / WSCALE;
    #pragma unroll
    for (int mt = 0; mt < 4; mt++) {
        #pragma unroll
        for (int hh = 0; hh < 2; hh++) {
            const int row = rowBase + wm * 64 + mt * 16 + g + hh * 8;
            const float rb = (EPI == 1) ? bias[row] : 0.f;
            #pragma unroll
            for (int nt = 0; nt < 8; nt++) {
                const int col = colBase + wn * 64 + nt * 8 + tig * 2;
                const float v0 = acc[mt][nt][hh * 2];
                const float v1 = acc[mt][nt][hh * 2 + 1];
                if (EPI == 0) {
                    __half h0, m0, h1, m1;
                    split2(v0, h0, m0);
                    split2(v1, h1, m1);
                    const size_t o = (size_t)row * N + col;
                    *reinterpret_cast<__half2*>(Oh + o) = __half2{h0, h1};
                    *reinterpret_cast<__half2*>(Om + o) = __half2{m0, m1};
                } else {
                    *reinterpret_cast<float2*>(outF + (size_t)row * N + col) =
                        make_float2(fmaf(v0, INVS, rb), fmaf(v1, INVS, rb));
                }
            }
        }
    }
}

// ---------------------------------------------------------------------------
// Row softmax over 4096 columns
// ---------------------------------------------------------------------------
__global__ __launch_bounds__(256) void softmax_kernel(const float* __restrict__ scores,
                                                      float* __restrict__ out) {
    const int i = blockIdx.x;
    const float4* row = reinterpret_cast<const float4*>(scores + (size_t)i * SEQ);
    float4* orow = reinterpret_cast<float4*>(out + (size_t)i * SEQ);

    float4 v[4];
    float m = -1e30f;
    #pragma unroll
    for (int t = 0; t < 4; t++) {
        v[t] = row[threadIdx.x + t * 256];
        m = fmaxf(m, fmaxf(fmaxf(v[t].x, v[t].y), fmaxf(v[t].z, v[t].w)));
    }
    __shared__ float red[8];
    #pragma unroll
    for (int o = 16; o; o >>= 1) m = fmaxf(m, __shfl_xor_sync(0xffffffffu, m, o));
    if ((threadIdx.x & 31) == 0) red[threadIdx.x >> 5] = m;
    __syncthreads();
    float m_all = red[0];
    #pragma unroll
    for (int k = 1; k < 8; k++) m_all = fmaxf(m_all, red[k]);
    __syncthreads();

    float s = 0.f;
    #pragma unroll
    for (int t = 0; t < 4; t++) {
        v[t].x = __expf(v[t].x - m_all);
        v[t].y = __expf(v[t].y - m_all);
        v[t].z = __expf(v[t].z - m_all);
        v[t].w = __expf(v[t].w - m_all);
        s += v[t].x + v[t].y + v[t].z + v[t].w;
    }
    #pragma unroll
    for (int o = 16; o; o >>= 1) s += __shfl_xor_sync(0xffffffffu, s, o);
    if ((threadIdx.x & 31) == 0) red[threadIdx.x >> 5] = s;
    __syncthreads();
    float s_all = 0.f;
    #pragma unroll
    for (int k = 0; k < 8; k++) s_all += red[k];
    const float inv = 1.0f / s_all;

    #pragma unroll
    for (int t = 0; t < 4; t++) {
        float4 o4 = make_float4(v[t].x * inv, v[t].y * inv, v[t].z * inv, v[t].w * inv);
        orow[threadIdx.x + t * 256] = o4;
    }
}

// ---------------------------------------------------------------------------
extern "C" void kernel_launch(void* const* d_in, const int* in_sizes, int n_in,
                              void* d_out, int out_size) {
    const float* out_state = (const float*)d_in[0];  // [2048, 2048]
    const float* history   = (const float*)d_in[1];  // [4096, 2048]
    const float* W         = (const float*)d_in[2];  // [2048, 2048]
    const float* b         = (const float*)d_in[3];  // [2048]
    float* out = (float*)d_out;                      // [2048, 4096]

    __half *osH, *osM, *wtH, *wtM, *hiH, *hiM, *tH, *tM;
    float *scores, *cvec;
    cudaGetSymbolAddress((void**)&osH, g_osH); cudaGetSymbolAddress((void**)&osM, g_osM);
    cudaGetSymbolAddress((void**)&wtH, g_wtH); cudaGetSymbolAddress((void**)&wtM, g_wtM);
    cudaGetSymbolAddress((void**)&hiH, g_hiH); cudaGetSymbolAddress((void**)&hiM, g_hiM);
    cudaGetSymbolAddress((void**)&tH, g_tH);   cudaGetSymbolAddress((void**)&tM, g_tM);
    cudaGetSymbolAddress((void**)&scores, g_scores);
    cudaGetSymbolAddress((void**)&cvec, g_c);

    cudaFuncSetAttribute(gemm_mma<0>, cudaFuncAttributeMaxDynamicSharedMemorySize,
                         (int)SMEM_TOTAL);
    cudaFuncSetAttribute(gemm_mma<1>, cudaFuncAttributeMaxDynamicSharedMemorySize,
                         (int)SMEM_TOTAL);

    // 1. splits
    split2_kernel<<<(S_LEN * HID / 4 + 255) / 256, 256>>>(out_state, osH, osM,
                                                          S_LEN * HID / 4);
    split2_kernel<<<(SEQ * HID / 4 + 255) / 256, 256>>>(history, hiH, hiM,
                                                        SEQ * HID / 4);
    splitWT_kernel<<<dim3(HID / 32, HID / 32), 256>>>(W, wtH, wtM);

    // 2. c[i] = out_state[i] . b
    dot_bias_kernel<<<S_LEN, 256>>>(out_state, b);

    // 3. T' = out_state @ (64*W); epilogue splits T' into fp16 planes
    gemm_mma<0><<<dim3(HID / NTILE, S_LEN / 128), 256, SMEM_TOTAL>>>(
        osH, osM, wtH, wtM, nullptr, tH, tM, nullptr, HID);

    // 4. scores = (T' @ history^T)/64 + c
    gemm_mma<1><<<dim3(SEQ / NTILE, S_LEN / 128), 256, SMEM_TOTAL>>>(
        tH, tM, hiH, hiM, scores, nullptr, nullptr, cvec, SEQ);

    // 5. softmax rows
    softmax_kernel<<<S_LEN, 256>>>(scores, out);
}

// round 6
// speedup vs baseline: 2.5731x; 1.0216x over previous
#include <cuda_runtime.h>
#include <cuda_fp16.h>
#include <cstdint>

constexpr int S_LEN = 2048;
constexpr int SEQ   = 4096;
constexpr int HID   = 2048;
constexpr int KDIM  = 2048;
constexpr float WSCALE = 64.0f;          // keep W's m-plane out of fp16 subnormals

// ---------------------------------------------------------------------------
// Scratch (__device__ globals; allocation-free rule)
// ---------------------------------------------------------------------------
__device__ __half g_osH[(size_t)S_LEN * HID];
__device__ __half g_osM[(size_t)S_LEN * HID];
__device__ __half g_wtH[(size_t)HID * HID];    // wt[k][h] = 64*W[h][k]
__device__ __half g_wtM[(size_t)HID * HID];
__device__ __half g_hiH[(size_t)SEQ * HID];
__device__ __half g_hiM[(size_t)SEQ * HID];
__device__ __half g_tH[(size_t)S_LEN * HID];   // planes of T' = 64*T
__device__ __half g_tM[(size_t)S_LEN * HID];
__device__ float g_scores[(size_t)S_LEN * SEQ];
__device__ float g_c[S_LEN];

// ---------------------------------------------------------------------------
// PTX helpers (sm_80-baseline features only: legal on .target sm_103)
// ---------------------------------------------------------------------------
__device__ __forceinline__ uint32_t smem_to_u32(const void* p) {
    uint32_t a;
    asm("{ .reg .u64 t; cvta.to.shared.u64 t, %1; cvt.u32.u64 %0, t; }" : "=r"(a) : "l"(p));
    return a;
}
__device__ __forceinline__ void cp16(uint32_t dst, const void* src) {
    asm volatile("cp.async.cg.shared.global [%0], [%1], 16;" :: "r"(dst), "l"(src));
}
__device__ __forceinline__ void cp_commit() {
    asm volatile("cp.async.commit_group;" ::: "memory");
}
template <int N>
__device__ __forceinline__ void cp_wait() {
    asm volatile("cp.async.wait_group %0;" :: "n"(N) : "memory");
}
__device__ __forceinline__ void ldm4(uint32_t* r, uint32_t addr) {
    asm volatile("ldmatrix.sync.aligned.m8n8.x4.shared.b16 {%0,%1,%2,%3}, [%4];"
                 : "=r"(r[0]), "=r"(r[1]), "=r"(r[2]), "=r"(r[3]) : "r"(addr));
}
__device__ __forceinline__ void mma16816(float* d, const uint32_t* a, const uint32_t* b) {
    asm volatile(
        "mma.sync.aligned.m16n8k16.row.col.f32.f16.f16.f32 "
        "{%0,%1,%2,%3}, {%4,%5,%6,%7}, {%8,%9}, {%0,%1,%2,%3};"
        : "+f"(d[0]), "+f"(d[1]), "+f"(d[2]), "+f"(d[3])
        : "r"(a[0]), "r"(a[1]), "r"(a[2]), "r"(a[3]), "r"(b[0]), "r"(b[1]));
}

// ---------------------------------------------------------------------------
// 2-way fp16 split helpers
// ---------------------------------------------------------------------------
__device__ __forceinline__ void split2(float a, __half& h, __half& m) {
    h = __float2half_rn(a);
    float r = a - __half2float(h);
    m = __float2half_rn(r);
}

__global__ __launch_bounds__(256) void split2_kernel(const float* __restrict__ in,
                                                     __half* __restrict__ oh,
                                                     __half* __restrict__ om,
                                                     int n4) {
    int i = blockIdx.x * 256 + threadIdx.x;
    if (i < n4) {
        float4 v = reinterpret_cast<const float4*>(in)[i];
        __half h[4], m[4];
        split2(v.x, h[0], m[0]);
        split2(v.y, h[1], m[1]);
        split2(v.z, h[2], m[2]);
        split2(v.w, h[3], m[3]);
        reinterpret_cast<__half2*>(oh)[i * 2]     = __half2{h[0], h[1]};
        reinterpret_cast<__half2*>(oh)[i * 2 + 1] = __half2{h[2], h[3]};
        reinterpret_cast<__half2*>(om)[i * 2]     = __half2{m[0], m[1]};
        reinterpret_cast<__half2*>(om)[i * 2 + 1] = __half2{m[2], m[3]};
    }
}

// W [h][k] row-major -> planes wt[k][h] = 64*W[h][k]   (transpose + scale)
__global__ __launch_bounds__(256) void splitWT_kernel(const float* __restrict__ W,
                                                      __half* __restrict__ oh,
                                                      __half* __restrict__ om) {
    __shared__ float tile[32][33];
    const int tx = threadIdx.x & 31;
    const int ty = threadIdx.x >> 5;
    const int k0 = blockIdx.x * 32;
    const int h0 = blockIdx.y * 32;
    #pragma unroll
    for (int j = 0; j < 32; j += 8)
        tile[ty + j][tx] = W[(size_t)(h0 + ty + j) * HID + k0 + tx];
    __syncthreads();
    #pragma unroll
    for (int j = 0; j < 32; j += 8) {
        float a = tile[tx][ty + j] * WSCALE;
        __half h, m;
        split2(a, h, m);
        size_t o = (size_t)(k0 + ty + j) * HID + h0 + tx;
        oh[o] = h; om[o] = m;
    }
}

// ---------------------------------------------------------------------------
// c[i] = out_state[i] . b
// ---------------------------------------------------------------------------
__global__ __launch_bounds__(256) void dot_bias_kernel(const float* __restrict__ A,
                                                       const float* __restrict__ b) {
    const int i = blockIdx.x;
    const float* row = A + (size_t)i * HID;
    float s = 0.f;
    for (int h = threadIdx.x * 4; h < HID; h += 256 * 4) {
        float4 x = *reinterpret_cast<const float4*>(row + h);
        float4 y = *reinterpret_cast<const float4*>(b + h);
        s += x.x * y.x + x.y * y.y + x.z * y.z + x.w * y.w;
    }
    __shared__ float red[8];
    #pragma unroll
    for (int o = 16; o; o >>= 1) s += __shfl_xor_sync(0xffffffffu, s, o);
    if ((threadIdx.x & 31) == 0) red[threadIdx.x >> 5] = s;
    __syncthreads();
    if (threadIdx.x == 0) {
        float t = 0.f;
        #pragma unroll
        for (int k = 0; k < 8; k++) t += red[k];
        g_c[i] = t;
    }
}

// ---------------------------------------------------------------------------
// HMMA emulated-fp32 GEMM: C[M,N] = A[M,K] @ B[N,K]^T  (2-plane fp16 splits)
// Products: hh, hm, mh.  CTA tile 128x256, 8 warps (2M x 4N), warp tile 64x64.
// K-chunk 32, 3-stage cp.async, SINGLE barrier per k-chunk (loads issued
// before compute into the stage freed by the previous iteration).
//   EPI=0: split C into fp16 h/m planes   EPI=1: C_f32 = C*(1/WSCALE) + bias[row]
// ---------------------------------------------------------------------------
constexpr int NTILE   = 256;
constexpr int KC      = 32;
constexpr int NC      = KDIM / KC;             // 64 chunks
constexpr int ROWB    = 80;                    // 64B data + 16B pad
constexpr int R_TOT   = 2 * (128 + NTILE);     // 768 rows per stage
constexpr int STAGE_B = R_TOT * ROWB;          // 61440
constexpr int NSTAGE  = 3;
constexpr size_t SMEM_TOTAL = (size_t)NSTAGE * STAGE_B;   // 184320
constexpr int PL_A0 = 0;            // Ah rows [0,128)
constexpr int PL_B0 = 256;          // Bh rows [0,NTILE)

template <int EPI>
__global__ __launch_bounds__(256, 1)
void gemm_mma(const __half* __restrict__ Ah, const __half* __restrict__ Am,
              const __half* __restrict__ Bh, const __half* __restrict__ Bm,
              float* __restrict__ outF, __half* __restrict__ Oh,
              __half* __restrict__ Om, const float* __restrict__ bias, int N) {
    extern __shared__ char smem[];
    const uint32_t sb = smem_to_u32(smem);
    const int tid  = threadIdx.x;
    const int lane = tid & 31;
    const int w    = tid >> 5;
    const int wm   = w & 1;        // 2 warps along M (64 rows each)
    const int wn   = w >> 1;       // 4 warps along N (64 cols each)
    const int rowBase = blockIdx.y * 128;
    const int colBase = blockIdx.x * NTILE;

    uint32_t aOff[4], bOff[4];
    #pragma unroll
    for (int mt = 0; mt < 4; mt++)
        aOff[mt] = (uint32_t)((wm * 64 + mt * 16 + (lane & 15)) * ROWB + ((lane >> 4) << 4));
    #pragma unroll
    for (int nb = 0; nb < 4; nb++)
        bOff[nb] = (uint32_t)((wn * 64 + nb * 16 + (lane & 7) + ((lane >> 4) << 3)) * ROWB
                              + (((lane >> 3) & 1) << 4));

    float acc[4][8][4];
    #pragma unroll
    for (int mt = 0; mt < 4; mt++)
        #pragma unroll
        for (int nt = 0; nt < 8; nt++)
            #pragma unroll
            for (int q = 0; q < 4; q++) acc[mt][nt][q] = 0.f;

    const int lr = tid >> 2;        // 0..63
    const int lc = tid & 3;         // 16B chunk within 64B row
    auto load_stage = [&](int kc) {
        const uint32_t dstStage = sb + (uint32_t)(kc % NSTAGE) * STAGE_B;
        const char* srcA[2] = {(const char*)(Ah + (size_t)(rowBase + lr) * KDIM + kc * KC),
                               (const char*)(Am + (size_t)(rowBase + lr) * KDIM + kc * KC)};
        const char* srcB[2] = {(const char*)(Bh + (size_t)(colBase + lr) * KDIM + kc * KC),
                               (const char*)(Bm + (size_t)(colBase + lr) * KDIM + kc * KC)};
        #pragma unroll
        for (int p = 0; p < 2; p++) {
            #pragma unroll
            for (int j = 0; j < 2; j++) {
                const int r = lr + j * 64;
                cp16(dstStage + (uint32_t)((PL_A0 + p * 128 + r) * ROWB + lc * 16),
                     srcA[p] + (size_t)j * 64 * KDIM * 2 + lc * 16);
            }
            #pragma unroll
            for (int j = 0; j < NTILE / 64; j++) {
                const int r = lr + j * 64;
                cp16(dstStage + (uint32_t)((PL_B0 + p * NTILE + r) * ROWB + lc * 16),
                     srcB[p] + (size_t)j * 64 * KDIM * 2 + lc * 16);
            }
        }
    };

    // prologue: NSTAGE-1 stages in flight
    load_stage(0); cp_commit();
    load_stage(1); cp_commit();

    for (int kc = 0; kc < NC; kc++) {
        cp_wait<NSTAGE - 2>();      // stage kc resident (<=1 group outstanding)
        __syncthreads();            // everyone done reading stage freed last iter

        // issue next load FIRST so DRAM fetch overlaps this chunk's MMAs
        if (kc + 2 < NC) load_stage(kc + 2);
        cp_commit();                // commit (possibly empty) group every iter

        const uint32_t base = sb + (uint32_t)(kc % NSTAGE) * STAGE_B;
        #pragma unroll
        for (int s = 0; s < 2; s++) {               // two k16 steps per chunk
            uint32_t af[2][4][4];
            #pragma unroll
            for (int pa = 0; pa < 2; pa++)
                #pragma unroll
                for (int mt = 0; mt < 4; mt++)
                    ldm4(af[pa][mt],
                         base + (uint32_t)((PL_A0 + pa * 128) * ROWB) + aOff[mt] + s * 32);
            #pragma unroll
            for (int pb = 0; pb < 2; pb++) {
                uint32_t bf[4][4];
                #pragma unroll
                for (int nb = 0; nb < 4; nb++)
                    ldm4(bf[nb],
                         base + (uint32_t)((PL_B0 + pb * NTILE) * ROWB) + bOff[nb] + s * 32);
                #pragma unroll
                for (int pa = 0; pa < 2; pa++) {
                    if (pa + pb > 1) continue;      // hh, hm, mh
                    #pragma unroll
                    for (int mt = 0; mt < 4; mt++)
                        #pragma unroll
                        for (int nt = 0; nt < 8; nt++)
                            mma16816(acc[mt][nt], af[pa][mt], &bf[nt >> 1][(nt & 1) * 2]);
                }
            }
        }
    }

    const int g   = lane >> 2;
    const int tig = lane & 3;
    constexpr float INVS = 1.0f / WSCALE;
    #pragma unroll
    for (int mt = 0; mt < 4; mt++) {
        #pragma unroll
        for (int hh = 0; hh < 2; hh++) {
            const int row = rowBase + wm * 64 + mt * 16 + g + hh * 8;
            const float rb = (EPI == 1) ? bias[row] : 0.f;
            #pragma unroll
            for (int nt = 0; nt < 8; nt++) {
                const int col = colBase + wn * 64 + nt * 8 + tig * 2;
                const float v0 = acc[mt][nt][hh * 2];
                const float v1 = acc[mt][nt][hh * 2 + 1];
                if (EPI == 0) {
                    __half h0, m0, h1, m1;
                    split2(v0, h0, m0);
                    split2(v1, h1, m1);
                    const size_t o = (size_t)row * N + col;
                    *reinterpret_cast<__half2*>(Oh + o) = __half2{h0, h1};
                    *reinterpret_cast<__half2*>(Om + o) = __half2{m0, m1};
                } else {
                    *reinterpret_cast<float2*>(outF + (size_t)row * N + col) =
                        make_float2(fmaf(v0, INVS, rb), fmaf(v1, INVS, rb));
                }
            }
        }
    }
}

// ---------------------------------------------------------------------------
// Row softmax over 4096 columns
// ---------------------------------------------------------------------------
__global__ __launch_bounds__(256) void softmax_kernel(const float* __restrict__ scores,
                                                      float* __restrict__ out) {
    const int i = blockIdx.x;
    const float4* row = reinterpret_cast<const float4*>(scores + (size_t)i * SEQ);
    float4* orow = reinterpret_cast<float4*>(out + (size_t)i * SEQ);

    float4 v[4];
    float m = -1e30f;
    #pragma unroll
    for (int t = 0; t < 4; t++) {
        v[t] = row[threadIdx.x + t * 256];
        m = fmaxf(m, fmaxf(fmaxf(v[t].x, v[t].y), fmaxf(v[t].z, v[t].w)));
    }
    __shared__ float red[8];
    #pragma unroll
    for (int o = 16; o; o >>= 1) m = fmaxf(m, __shfl_xor_sync(0xffffffffu, m, o));
    if ((threadIdx.x & 31) == 0) red[threadIdx.x >> 5] = m;
    __syncthreads();
    float m_all = red[0];
    #pragma unroll
    for (int k = 1; k < 8; k++) m_all = fmaxf(m_all, red[k]);
    __syncthreads();

    float s = 0.f;
    #pragma unroll
    for (int t = 0; t < 4; t++) {
        v[t].x = __expf(v[t].x - m_all);
        v[t].y = __expf(v[t].y - m_all);
        v[t].z = __expf(v[t].z - m_all);
        v[t].w = __expf(v[t].w - m_all);
        s += v[t].x + v[t].y + v[t].z + v[t].w;
    }
    #pragma unroll
    for (int o = 16; o; o >>= 1) s += __shfl_xor_sync(0xffffffffu, s, o);
    if ((threadIdx.x & 31) == 0) red[threadIdx.x >> 5] = s;
    __syncthreads();
    float s_all = 0.f;
    #pragma unroll
    for (int k = 0; k < 8; k++) s_all += red[k];
    const float inv = 1.0f / s_all;

    #pragma unroll
    for (int t = 0; t < 4; t++) {
        float4 o4 = make_float4(v[t].x * inv, v[t].y * inv, v[t].z * inv, v[t].w * inv);
        orow[threadIdx.x + t * 256] = o4;
    }
}

// ---------------------------------------------------------------------------
extern "C" void kernel_launch(void* const* d_in, const int* in_sizes, int n_in,
                              void* d_out, int out_size) {
    const float* out_state = (const float*)d_in[0];  // [2048, 2048]
    const float* history   = (const float*)d_in[1];  // [4096, 2048]
    const float* W         = (const float*)d_in[2];  // [2048, 2048]
    const float* b         = (const float*)d_in[3];  // [2048]
    float* out = (float*)d_out;                      // [2048, 4096]

    __half *osH, *osM, *wtH, *wtM, *hiH, *hiM, *tH, *tM;
    float *scores, *cvec;
    cudaGetSymbolAddress((void**)&osH, g_osH); cudaGetSymbolAddress((void**)&osM, g_osM);
    cudaGetSymbolAddress((void**)&wtH, g_wtH); cudaGetSymbolAddress((void**)&wtM, g_wtM);
    cudaGetSymbolAddress((void**)&hiH, g_hiH); cudaGetSymbolAddress((void**)&hiM, g_hiM);
    cudaGetSymbolAddress((void**)&tH, g_tH);   cudaGetSymbolAddress((void**)&tM, g_tM);
    cudaGetSymbolAddress((void**)&scores, g_scores);
    cudaGetSymbolAddress((void**)&cvec, g_c);

    cudaFuncSetAttribute(gemm_mma<0>, cudaFuncAttributeMaxDynamicSharedMemorySize,
                         (int)SMEM_TOTAL);
    cudaFuncSetAttribute(gemm_mma<1>, cudaFuncAttributeMaxDynamicSharedMemorySize,
                         (int)SMEM_TOTAL);

    // 1. splits
    split2_kernel<<<(S_LEN * HID / 4 + 255) / 256, 256>>>(out_state, osH, osM,
                                                          S_LEN * HID / 4);
    split2_kernel<<<(SEQ * HID / 4 + 255) / 256, 256>>>(history, hiH, hiM,
                                                        SEQ * HID / 4);
    splitWT_kernel<<<dim3(HID / 32, HID / 32), 256>>>(W, wtH, wtM);

    // 2. c[i] = out_state[i] . b
    dot_bias_kernel<<<S_LEN, 256>>>(out_state, b);

    // 3. T' = out_state @ (64*W); epilogue splits T' into fp16 planes
    gemm_mma<0><<<dim3(HID / NTILE, S_LEN / 128), 256, SMEM_TOTAL>>>(
        osH, osM, wtH, wtM, nullptr, tH, tM, nullptr, HID);

    // 4. scores = (T' @ history^T)/64 + c
    gemm_mma<1><<<dim3(SEQ / NTILE, S_LEN / 128), 256, SMEM_TOTAL>>>(
        tH, tM, hiH, hiM, scores, nullptr, nullptr, cvec, SEQ);

    // 5. softmax rows
    softmax_kernel<<<S_LEN, 256>>>(scores, out);
}